// round 9
// baseline (speedup 1.0000x reference)
#include <cuda_runtime.h>

// CharAttention: B=512, W=128, c=24, C=32, H=2, D=16.
// Only the row at x_end_idx is needed -> one causal attention row per (b,w)
// tile with folded weights:
//   M_h = W_q_h @ W_k_h^T / sqrt(D)   (score_h(k) = x_q M_h x_k^T)
//   P_h = W_v_h @ W_proj[h*D:(h+1)*D] (y = sum_h (sum_k att_hk x_k) P_h)
// out = x[idx] + y.
// R2: warp-pair per tile (one head each), 64 weight regs/thread.
// R3: software pipeline — double-buffered x tile, one bar/tile.  [73.0 us]
// R6: + no softmax max-shift, overlapped sum reduce.             [67.5 us]
// R7: 2-acc matvecs: NEUTRAL -> not chain-bound; smem-wavefront bound.
// R8: key-range split across the warp pair: each warp scores & reduces
//     BOTH heads over HALF the keys (halves score row reads and s-loop
//     traffic), partial sums/s exchanged via smem + 1 extra bar; q read
//     directly from xs row (no register-copy round trip).

#define NTILES (512 * 128)
#define CBLK 24
#define EMB 32
#define XSTRIDE 36      // pad (mult of 4, %32==4): conflict-free float4-row AND scalar-column
#define PAIRS_PER_BLK 4
#define THREADS (PAIRS_PER_BLK * 64)
#define GRID 296        // 2 blocks/SM * 148 SMs -> fully persistent
#define PAIRSTRIDE (GRID * PAIRS_PER_BLK)

__device__ float g_M[2 * 32 * 32];  // [h][i][j]
__device__ float g_P[2 * 32 * 32];  // [h][i][j]

__global__ void precompute_kernel(const float* __restrict__ w_attn,
                                  const float* __restrict__ w_proj) {
    int t = blockIdx.x * blockDim.x + threadIdx.x;
    if (t >= 4096) return;
    int which = t >> 11;   // 0 = M, 1 = P
    int r = t & 2047;
    int h = r >> 10;
    int i = (r >> 5) & 31;
    int j = r & 31;
    float acc = 0.f;
    if (which == 0) {
        #pragma unroll
        for (int d = 0; d < 16; d++)
            acc += w_attn[i * 96 + h * 16 + d] * w_attn[j * 96 + 32 + h * 16 + d];
        g_M[r] = acc * 0.25f;  // 1/sqrt(16)
    } else {
        #pragma unroll
        for (int d = 0; d < 16; d++)
            acc += w_attn[i * 96 + 64 + h * 16 + d] * w_proj[(h * 16 + d) * 32 + j];
        g_P[r] = acc;
    }
}

__global__ void __launch_bounds__(THREADS, 2)
attn_kernel(const float* __restrict__ x, const int* __restrict__ endidx,
            float* __restrict__ out) {
    __shared__ __align__(16) float xs[2][PAIRS_PER_BLK][CBLK][XSTRIDE];
    __shared__ float4 us4[2 * PAIRS_PER_BLK][8];       // per-warp u_h (pair-shared)
    __shared__ float4 ss4[2 * PAIRS_PER_BLK][8];       // per-warp s_h
    __shared__ float2 atts2[PAIRS_PER_BLK][32];        // (e0,e1) per key, pair-shared
    __shared__ __align__(16) float2 sums[PAIRS_PER_BLK][2];  // per-warp (psum0,psum1)
    __shared__ float  xch[PAIRS_PER_BLK][2][32];       // cross-head partial s
    __shared__ float  y1s[PAIRS_PER_BLK][2][32];       // head-1 output, parity-buffered

    const int w    = threadIdx.x >> 5;
    const int lane = threadIdx.x & 31;
    const int p    = w >> 1;             // pair in block
    const int h    = w & 1;              // head owned by this warp
    const int pt   = (h << 5) | lane;    // thread within pair (0..63)
    const int barId = p + 1;

    // This warp's head's folded-weight columns (lane = output dim j).
    float Mc[32], Pc[32];
    {
        const float* Mb = g_M + h * 1024 + lane;
        const float* Pb = g_P + h * 1024 + lane;
        #pragma unroll
        for (int i = 0; i < 32; i++) { Mc[i] = Mb[i * 32]; Pc[i] = Pb[i * 32]; }
    }

    int bw = blockIdx.x * PAIRS_PER_BLK + p;

    // ---- Pipeline prologue: idx two tiles ahead, x one tile ahead.
    int id  = __ldg(endidx + bw);                                 // tile n
    int bw1 = bw + PAIRSTRIDE;
    int id1 = (bw1 < NTILES) ? __ldg(endidx + bw1) : 0;           // tile n+1

    float4 v[3];
    {
        const float* xt = x + (size_t)bw * (CBLK * EMB);
        const int totalF = (id + 1) * EMB;
        #pragma unroll
        for (int k = 0; k < 3; k++) {
            int e = pt * 4 + k * 256;
            if (e < totalF) v[k] = *reinterpret_cast<const float4*>(xt + e);
        }
    }

    int buf = 0;
    int   prev_bw = -1;
    float prev_qv = 0.f, prev_y = 0.f;

    while (bw < NTILES) {
        const int nk = id + 1;

        // ---- Commit staged tile n to smem.
        {
            const int totalF = nk * EMB;
            #pragma unroll
            for (int k = 0; k < 3; k++) {
                int e = pt * 4 + k * 256;
                if (e < totalF)
                    *reinterpret_cast<float4*>(&xs[buf][p][e >> 5][e & 31]) = v[k];
            }
        }
        asm volatile("bar.sync %0, 64;" :: "r"(barId) : "memory");

        // ---- Prefetch first (longest latency): idx n+2, x tile n+1.
        const int bw2 = bw1 + PAIRSTRIDE;
        const int id2 = (bw2 < NTILES) ? __ldg(endidx + bw2) : 0;
        if (bw1 < NTILES) {
            const float* xt = x + (size_t)bw1 * (CBLK * EMB);
            const int totalF = (id1 + 1) * EMB;
            #pragma unroll
            for (int k = 0; k < 3; k++) {
                int e = pt * 4 + k * 256;
                if (e < totalF) v[k] = *reinterpret_cast<const float4*>(xt + e);
            }
        }

        // ---- Store tile n-1 output (warp0); y1s written by warp1 pre-bar.
        if (h == 0 && prev_bw >= 0)
            out[prev_bw * EMB + lane] = prev_qv + prev_y + y1s[p][buf ^ 1][lane];

        // ---- u = q @ M_h; q read directly from xs row id (broadcast float4s).
        const float qv = xs[buf][p][id][lane];   // residual (column, conflict-free)
        const float4* qr = reinterpret_cast<const float4*>(&xs[buf][p][id][0]);
        float u0 = 0.f, u1 = 0.f;
        #pragma unroll
        for (int i4 = 0; i4 < 8; i4 += 2) {
            const float4 qa = qr[i4];
            const int i = i4 * 4;
            u0 = fmaf(qa.x, Mc[i + 0], u0);
            u0 = fmaf(qa.y, Mc[i + 1], u0);
            u0 = fmaf(qa.z, Mc[i + 2], u0);
            u0 = fmaf(qa.w, Mc[i + 3], u0);
            const float4 qb = qr[i4 + 1];
            u1 = fmaf(qb.x, Mc[i + 4], u1);
            u1 = fmaf(qb.y, Mc[i + 5], u1);
            u1 = fmaf(qb.z, Mc[i + 6], u1);
            u1 = fmaf(qb.w, Mc[i + 7], u1);
        }
        reinterpret_cast<float*>(us4[w])[lane] = u0 + u1;
        asm volatile("bar.sync %0, 64;" :: "r"(barId) : "memory");  // u visible pair-wide

        // ---- Key-range split: warp h handles keys [base, base+cnt) for BOTH heads.
        const int nk2  = (nk + 1) >> 1;
        const int base = h ? nk2 : 0;
        const int cnt  = h ? (nk - nk2) : nk2;

        float e0 = 0.f, e1 = 0.f;
        if ((unsigned)(lane - base) < (unsigned)cnt) {
            const float4* xr = reinterpret_cast<const float4*>(&xs[buf][p][lane][0]);
            const float4* uA = us4[2 * p];       // head0 u
            const float4* uB = us4[2 * p + 1];   // head1 u
            float a0 = 0.f, a1 = 0.f, b0 = 0.f, b1 = 0.f;
            #pragma unroll
            for (int i4 = 0; i4 < 8; i4 += 2) {
                const float4 xa = xr[i4];
                const float4 ua = uA[i4];
                const float4 va = uB[i4];
                a0 = fmaf(ua.x, xa.x, a0); a0 = fmaf(ua.y, xa.y, a0);
                a0 = fmaf(ua.z, xa.z, a0); a0 = fmaf(ua.w, xa.w, a0);
                b0 = fmaf(va.x, xa.x, b0); b0 = fmaf(va.y, xa.y, b0);
                b0 = fmaf(va.z, xa.z, b0); b0 = fmaf(va.w, xa.w, b0);
                const float4 xb = xr[i4 + 1];
                const float4 ub = uA[i4 + 1];
                const float4 vb = uB[i4 + 1];
                a1 = fmaf(ub.x, xb.x, a1); a1 = fmaf(ub.y, xb.y, a1);
                a1 = fmaf(ub.z, xb.z, a1); a1 = fmaf(ub.w, xb.w, a1);
                b1 = fmaf(vb.x, xb.x, b1); b1 = fmaf(vb.y, xb.y, b1);
                b1 = fmaf(vb.z, xb.z, b1); b1 = fmaf(vb.w, xb.w, b1);
            }
            // No max-shift: std(sc)=4, overflow needs sc>88 (22 sigma) — safe.
            e0 = __expf(a0 + a1);
            e1 = __expf(b0 + b1);
            atts2[p][lane] = make_float2(e0, e1);
        }
        __syncwarp();

        // ---- partial softmax sums over this warp's key range (both heads).
        float ps0 = e0, ps1 = e1;
        #pragma unroll
        for (int o = 16; o > 0; o >>= 1) {
            ps0 += __shfl_xor_sync(0xffffffffu, ps0, o);
            ps1 += __shfl_xor_sync(0xffffffffu, ps1, o);
        }
        if (lane == 0) sums[p][h] = make_float2(ps0, ps1);

        // ---- partial s over own range (own atts -> no bar needed), both heads.
        float pa0 = 0.f, pa1 = 0.f;
        for (int r = base; r < base + cnt; r++) {
            const float2 at = atts2[p][r];         // broadcast
            const float xv = xs[buf][p][r][lane];  // column, conflict-free
            pa0 = fmaf(at.x, xv, pa0);
            pa1 = fmaf(at.y, xv, pa1);
        }
        xch[p][h][lane] = h ? pa0 : pa1;   // publish my partial of the OTHER head
        asm volatile("bar.sync %0, 64;" :: "r"(barId) : "memory");

        // ---- combine partials + normalize: s_h = (mine + other)/sum_h.
        const float4 sv4 = *reinterpret_cast<const float4*>(&sums[p][0]);
        const float mysum = h ? (sv4.y + sv4.w) : (sv4.x + sv4.z);
        const float other = xch[p][h ^ 1][lane];   // other warp's partial of MY head
        const float mine  = h ? pa1 : pa0;
        const float s = __fdividef(mine + other, mysum);
        reinterpret_cast<float*>(ss4[w])[lane] = s;
        __syncwarp();

        // ---- y_h = s @ P_h   (lane = output dim j)
        float y0 = 0.f, y1 = 0.f;
        #pragma unroll
        for (int i4 = 0; i4 < 8; i4 += 2) {
            const float4 sa = ss4[w][i4];
            const int i = i4 * 4;
            y0 = fmaf(sa.x, Pc[i + 0], y0);
            y0 = fmaf(sa.y, Pc[i + 1], y0);
            y0 = fmaf(sa.z, Pc[i + 2], y0);
            y0 = fmaf(sa.w, Pc[i + 3], y0);
            const float4 sb = ss4[w][i4 + 1];
            y1 = fmaf(sb.x, Pc[i + 4], y1);
            y1 = fmaf(sb.y, Pc[i + 5], y1);
            y1 = fmaf(sb.z, Pc[i + 6], y1);
            y1 = fmaf(sb.w, Pc[i + 7], y1);
        }
        const float y = y0 + y1;

        // ---- defer combine: warp1 publishes, warp0 stores after next bar.
        if (h == 1) {
            y1s[p][buf][lane] = y;
        } else {
            prev_qv = qv; prev_y = y; prev_bw = bw;
        }

        bw = bw1; id = id1;
        bw1 = bw2; id1 = id2;
        buf ^= 1;
    }

    // ---- Epilogue: flush last tile's output.
    asm volatile("bar.sync %0, 64;" :: "r"(barId) : "memory");
    if (h == 0 && prev_bw >= 0)
        out[prev_bw * EMB + lane] = prev_qv + prev_y + y1s[p][buf ^ 1][lane];
}

extern "C" void kernel_launch(void* const* d_in, const int* in_sizes, int n_in,
                              void* d_out, int out_size) {
    const float* x      = (const float*)d_in[0];
    const int*   endidx = (const int*)d_in[1];
    const float* w_attn = (const float*)d_in[2];
    const float* w_proj = (const float*)d_in[3];
    float* out = (float*)d_out;

    precompute_kernel<<<16, 256>>>(w_attn, w_proj);
    attn_kernel<<<GRID, THREADS>>>(x, endidx, out);
}

// round 10
// speedup vs baseline: 1.1409x; 1.1409x over previous
#include <cuda_runtime.h>

// CharAttention: B=512, W=128, c=24, C=32, H=2, D=16.
// Only the row at x_end_idx is needed -> one causal attention row per (b,w)
// tile with folded weights:
//   M_h = W_q_h @ W_k_h^T / sqrt(D)   (score_h(k) = x_q M_h x_k^T)
//   P_h = W_v_h @ W_proj[h*D:(h+1)*D] (y = sum_h (sum_k att_hk x_k) P_h)
// out = x[idx] + y.
// R2: warp-pair per tile (one head each), 64 weight regs/thread.
// R3: software pipeline — double-buffered x tile, one bar/tile.  [73.0 us]
// R6: + no softmax max-shift, overlapped sum reduce.             [67.5 us]
// R7: 2-acc matvecs NEUTRAL; R8: key-split REGRESSED (bars+instr dominate).
// R9: R6 skeleton + branch-free s-phase: atts zero-padded to 32 lanes,
//     s-loop fully unrolled over ALL 24 rows (0-contribution beyond nk),
//     atts pre-loaded as 6 float4 broadcasts, 2 accumulators.
//     xs zero-initialized once so stale rows are finite (0 x finite = 0).

#define NTILES (512 * 128)
#define CBLK 24
#define EMB 32
#define XSTRIDE 36      // pad (mult of 4, %32==4): conflict-free float4-row AND scalar-column
#define PAIRS_PER_BLK 4
#define THREADS (PAIRS_PER_BLK * 64)
#define GRID 296        // 2 blocks/SM * 148 SMs -> fully persistent
#define PAIRSTRIDE (GRID * PAIRS_PER_BLK)

__device__ float g_M[2 * 32 * 32];  // [h][i][j]
__device__ float g_P[2 * 32 * 32];  // [h][i][j]

__global__ void precompute_kernel(const float* __restrict__ w_attn,
                                  const float* __restrict__ w_proj) {
    int t = blockIdx.x * blockDim.x + threadIdx.x;
    if (t >= 4096) return;
    int which = t >> 11;   // 0 = M, 1 = P
    int r = t & 2047;
    int h = r >> 10;
    int i = (r >> 5) & 31;
    int j = r & 31;
    float acc = 0.f;
    if (which == 0) {
        #pragma unroll
        for (int d = 0; d < 16; d++)
            acc += w_attn[i * 96 + h * 16 + d] * w_attn[j * 96 + 32 + h * 16 + d];
        g_M[r] = acc * 0.25f;  // 1/sqrt(16)
    } else {
        #pragma unroll
        for (int d = 0; d < 16; d++)
            acc += w_attn[i * 96 + 64 + h * 16 + d] * w_proj[(h * 16 + d) * 32 + j];
        g_P[r] = acc;
    }
}

__global__ void __launch_bounds__(THREADS, 2)
attn_kernel(const float* __restrict__ x, const int* __restrict__ endidx,
            float* __restrict__ out) {
    __shared__ __align__(16) float xs[2][PAIRS_PER_BLK][CBLK][XSTRIDE];
    __shared__ float4 qs4[2 * PAIRS_PER_BLK][8];   // per-warp private q copy
    __shared__ float4 us4[2 * PAIRS_PER_BLK][8];   // per-warp u_h
    __shared__ float4 ss4[2 * PAIRS_PER_BLK][8];   // per-warp s_h
    __shared__ __align__(16) float atts[2 * PAIRS_PER_BLK][32];  // zero-padded
    __shared__ float  y1s[PAIRS_PER_BLK][2][32];   // head-1 output, parity-buffered

    const int w    = threadIdx.x >> 5;
    const int lane = threadIdx.x & 31;
    const int p    = w >> 1;             // pair in block
    const int h    = w & 1;              // head handled by this warp
    const int pt   = (h << 5) | lane;    // thread within pair (0..63)
    const int barId = p + 1;

    // Zero-init xs once: stale rows beyond nk are multiplied by att=0 in the
    // unrolled s-phase; they must be finite (0 * NaN != 0).
    {
        float* z = &xs[0][0][0][0];
        const int total = 2 * PAIRS_PER_BLK * CBLK * XSTRIDE;
        for (int i = threadIdx.x; i < total; i += THREADS) z[i] = 0.f;
        __syncthreads();
    }

    // This warp's head's folded-weight columns (lane = output dim j).
    float Mc[32], Pc[32];
    {
        const float* Mb = g_M + h * 1024 + lane;
        const float* Pb = g_P + h * 1024 + lane;
        #pragma unroll
        for (int i = 0; i < 32; i++) { Mc[i] = Mb[i * 32]; Pc[i] = Pb[i * 32]; }
    }

    int bw = blockIdx.x * PAIRS_PER_BLK + p;

    // ---- Pipeline prologue: idx two tiles ahead, x one tile ahead.
    int id  = __ldg(endidx + bw);                                 // tile n
    int bw1 = bw + PAIRSTRIDE;
    int id1 = (bw1 < NTILES) ? __ldg(endidx + bw1) : 0;           // tile n+1

    float4 v[3];
    {
        const float* xt = x + (size_t)bw * (CBLK * EMB);
        const int totalF = (id + 1) * EMB;
        #pragma unroll
        for (int k = 0; k < 3; k++) {
            int e = pt * 4 + k * 256;
            if (e < totalF) v[k] = *reinterpret_cast<const float4*>(xt + e);
        }
    }

    int buf = 0;
    int   prev_bw = -1;
    float prev_qv = 0.f, prev_y = 0.f;

    while (bw < NTILES) {
        const int nk = id + 1;

        // ---- Commit staged tile n to smem.
        {
            const int totalF = nk * EMB;
            #pragma unroll
            for (int k = 0; k < 3; k++) {
                int e = pt * 4 + k * 256;
                if (e < totalF)
                    *reinterpret_cast<float4*>(&xs[buf][p][e >> 5][e & 31]) = v[k];
            }
        }
        asm volatile("bar.sync %0, 64;" :: "r"(barId) : "memory");

        // ---- Store tile n-1 output (warp0); y1s written by warp1 pre-bar.
        if (h == 0 && prev_bw >= 0)
            out[prev_bw * EMB + lane] = prev_qv + prev_y + y1s[p][buf ^ 1][lane];

        // ---- Prefetch: idx for tile n+2, x for tile n+1 (latency hidden
        //      behind this tile's compute).
        const int bw2 = bw1 + PAIRSTRIDE;
        const int id2 = (bw2 < NTILES) ? __ldg(endidx + bw2) : 0;
        if (bw1 < NTILES) {
            const float* xt = x + (size_t)bw1 * (CBLK * EMB);
            const int totalF = (id1 + 1) * EMB;
            #pragma unroll
            for (int k = 0; k < 3; k++) {
                int e = pt * 4 + k * 256;
                if (e < totalF) v[k] = *reinterpret_cast<const float4*>(xt + e);
            }
        }

        // ---- q = x[idx] (conflict-free column read); private warp copy.
        const float qv = xs[buf][p][id][lane];
        reinterpret_cast<float*>(qs4[w])[lane] = qv;
        __syncwarp();

        // ---- u = q @ M_h   (lane = output dim j)
        float u = 0.f;
        #pragma unroll
        for (int i4 = 0; i4 < 8; i4++) {
            const float4 q = qs4[w][i4];
            const int i = i4 * 4;
            u = fmaf(q.x, Mc[i + 0], u);
            u = fmaf(q.y, Mc[i + 1], u);
            u = fmaf(q.z, Mc[i + 2], u);
            u = fmaf(q.w, Mc[i + 3], u);
        }
        reinterpret_cast<float*>(us4[w])[lane] = u;
        __syncwarp();

        // ---- scores: lane = key r; sc = u . x_r (float4 row reads)
        float e = 0.f;
        if (lane < nk) {
            const float4* xr = reinterpret_cast<const float4*>(&xs[buf][p][lane][0]);
            float a = 0.f;
            #pragma unroll
            for (int i4 = 0; i4 < 8; i4++) {
                const float4 uu = us4[w][i4];   // broadcast
                const float4 xv = xr[i4];
                a = fmaf(uu.x, xv.x, a);
                a = fmaf(uu.y, xv.y, a);
                a = fmaf(uu.z, xv.z, a);
                a = fmaf(uu.w, xv.w, a);
            }
            // No max-shift: std(sc)=4, overflow needs sc>88 (22 sigma) — safe.
            e = __expf(a);
        }
        atts[w][lane] = e;   // e == 0 for lane >= nk: zero-padded
        __syncwarp();

        // ---- sum reduce; issues alongside the s-phase (consumed at divide).
        float sum = e;
        #pragma unroll
        for (int o = 16; o > 0; o >>= 1)
            sum += __shfl_xor_sync(0xffffffffu, sum, o);

        // ---- s = sum_r att_r * x_r over ALL 24 rows, branch-free.
        //      atts pre-loaded as 6 float4 broadcasts; rows >= nk contribute 0.
        {
            const float4* a4 = reinterpret_cast<const float4*>(atts[w]);
            const float*  xc = &xs[buf][p][0][lane];
            float s0 = 0.f, s1 = 0.f;
            #pragma unroll
            for (int r4 = 0; r4 < 6; r4++) {
                const float4 at = a4[r4];
                const int r = r4 * 4;
                s0 = fmaf(at.x, xc[(r + 0) * XSTRIDE], s0);
                s1 = fmaf(at.y, xc[(r + 1) * XSTRIDE], s1);
                s0 = fmaf(at.z, xc[(r + 2) * XSTRIDE], s0);
                s1 = fmaf(at.w, xc[(r + 3) * XSTRIDE], s1);
            }
            const float s = __fdividef(s0 + s1, sum);
            reinterpret_cast<float*>(ss4[w])[lane] = s;
        }
        __syncwarp();

        // ---- y_h = s @ P_h   (lane = output dim j)
        float y = 0.f;
        #pragma unroll
        for (int i4 = 0; i4 < 8; i4++) {
            const float4 sv = ss4[w][i4];
            const int i = i4 * 4;
            y = fmaf(sv.x, Pc[i + 0], y);
            y = fmaf(sv.y, Pc[i + 1], y);
            y = fmaf(sv.z, Pc[i + 2], y);
            y = fmaf(sv.w, Pc[i + 3], y);
        }

        // ---- defer combine: warp1 publishes, warp0 stores after next bar.
        if (h == 1) {
            y1s[p][buf][lane] = y;
        } else {
            prev_qv = qv; prev_y = y; prev_bw = bw;
        }

        bw = bw1; id = id1;
        bw1 = bw2; id1 = id2;
        buf ^= 1;
    }

    // ---- Epilogue: flush last tile's output.
    asm volatile("bar.sync %0, 64;" :: "r"(barId) : "memory");
    if (h == 0 && prev_bw >= 0)
        out[prev_bw * EMB + lane] = prev_qv + prev_y + y1s[p][buf ^ 1][lane];
}

extern "C" void kernel_launch(void* const* d_in, const int* in_sizes, int n_in,
                              void* d_out, int out_size) {
    const float* x      = (const float*)d_in[0];
    const int*   endidx = (const int*)d_in[1];
    const float* w_attn = (const float*)d_in[2];
    const float* w_proj = (const float*)d_in[3];
    float* out = (float*)d_out;

    precompute_kernel<<<16, 256>>>(w_attn, w_proj);
    attn_kernel<<<GRID, THREADS>>>(x, endidx, out);
}